// round 6
// baseline (speedup 1.0000x reference)
#include <cuda_runtime.h>
#include <cstdint>

// ---------------------------------------------------------------------------
// NoteAxis: 2-layer LSTM, B=4096, U=128, 128 steps, teacher-forced.
// Persistent fp32 kernel, packed fma.rn.f32x2 (2 batch rows per register).
// 128 CTAs x 512 threads; CTA owns 32 batch rows for all steps.
// Weights pre-transposed AND pre-duplicated ((w,w) float2) so every shared
// load is directly an f32x2 operand: per k-iter a thread issues only
// 2x LDS.128 (x pairs) + 4x LDS.64 (w) + 16 FFMA2.
// Single-sync-per-chunk cp.async double buffering. Cell state in registers.
// ---------------------------------------------------------------------------

#define B_TOTAL   4096
#define NSTEP     128
#define FDIM      127
#define UNITS     128
#define GATES     512              // 4*U
#define KDIM      256              // [x | h]
#define BT        32               // batch rows per CTA
#define NCTA      (B_TOTAL / BT)   // 128
#define NTHREAD   512
#define KC        16               // k rows per staged chunk
#define NCHUNK    (KDIM / KC)      // 16
#define ROWPAD    36               // sX row stride (floats), 16B aligned
#define ROWBYTES  (ROWPAD * 4)     // 144
#define CHUNK_F2     (KC * GATES)          // 8192 float2
#define CHUNK_FLOATS (CHUNK_F2 * 2)        // 16384 floats
#define CHUNK_BYTES  (CHUNK_FLOATS * 4)    // 65536

// shared layout (float offsets)
#define OFF_X0    0
#define OFF_X1    (KDIM * ROWPAD)              // 9216
#define OFF_W     (2 * KDIM * ROWPAD)          // 18432
#define OFF_B0D   (OFF_W + 2 * CHUNK_FLOATS)   // 51200 (512 float2 dup'd)
#define OFF_B1D   (OFF_B0D + 2 * GATES)        // 52224
#define OFF_WO    (OFF_B1D + 2 * GATES)        // 53248
#define OFF_BO    (OFF_WO + UNITS)             // 53376
#define SMEM_FLOATS (OFF_BO + 4)               // 53380
#define SMEM_BYTES  (SMEM_FLOATS * 4)          // 213520 (~208.5 KB)

// ---------------- persistent device scratch (no runtime alloc) -------------
__device__ float2 g_Wt0[KDIM * GATES];   // [k][c], value duplicated (w,w)
__device__ float2 g_Wt1[KDIM * GATES];
__device__ float2 g_b0d[GATES];          // (b,b) with b = b_ih + b_hh
__device__ float2 g_b1d[GATES];
__device__ float  g_wout[UNITS];
__device__ float  g_bout[1];

// ---------------------------------------------------------------------------
__global__ void noteaxis_prep(const float* __restrict__ wih0, const float* __restrict__ whh0,
                              const float* __restrict__ bih0, const float* __restrict__ bhh0,
                              const float* __restrict__ wih1, const float* __restrict__ whh1,
                              const float* __restrict__ bih1, const float* __restrict__ bhh1,
                              const float* __restrict__ wout, const float* __restrict__ bout)
{
    int idx = blockIdx.x * blockDim.x + threadIdx.x;
    if (idx < KDIM * GATES) {
        int k = idx >> 9;       // 0..255
        int c = idx & 511;      // 0..511
        float w0 = (k < UNITS) ? wih0[c * UNITS + k] : whh0[c * UNITS + (k - UNITS)];
        float w1 = (k < UNITS) ? wih1[c * UNITS + k] : whh1[c * UNITS + (k - UNITS)];
        g_Wt0[idx] = make_float2(w0, w0);
        g_Wt1[idx] = make_float2(w1, w1);
    }
    if (idx < GATES) {
        float b0 = bih0[idx] + bhh0[idx];
        float b1 = bih1[idx] + bhh1[idx];
        g_b0d[idx] = make_float2(b0, b0);
        g_b1d[idx] = make_float2(b1, b1);
    }
    if (idx < UNITS) g_wout[idx] = wout[idx];
    if (idx == 0)    g_bout[0]   = bout[0];
}

// ---------------------------------------------------------------------------
__device__ __forceinline__ float ftanh_(float x) {
    float r;
    asm("tanh.approx.f32 %0, %1;" : "=f"(r) : "f"(x));
    return r;
}
__device__ __forceinline__ float fsig(float x) {
    // sigmoid(x) = 0.5*tanh(0.5x) + 0.5   (1 MUFU + 1 FMA)
    return fmaf(0.5f, ftanh_(0.5f * x), 0.5f);
}
__device__ __forceinline__ void unpack2(unsigned long long v, float& lo, float& hi) {
    asm("mov.b64 {%0, %1}, %2;" : "=f"(lo), "=f"(hi) : "l"(v));
}
__device__ __forceinline__ unsigned long long pack2(float lo, float hi) {
    unsigned long long v;
    asm("mov.b64 %0, {%1, %2};" : "=l"(v) : "f"(lo), "f"(hi));
    return v;
}

// Stage one KC x 512 dup'd weight chunk (64 KB) gmem -> smem via cp.async.cg.
__device__ __forceinline__ void prefetch_chunk(uint32_t dst_smem, const float2* __restrict__ src, int tid) {
    const char* s = reinterpret_cast<const char*>(src) + tid * 16;
    uint32_t d = dst_smem + tid * 16;
#pragma unroll
    for (int r = 0; r < 8; ++r) {
        asm volatile("cp.async.cg.shared.global [%0], [%1], 16;" :: "r"(d), "l"(s) : "memory");
        d += NTHREAD * 16;
        s += NTHREAD * 16;
    }
    asm volatile("cp.async.commit_group;" ::: "memory");
}

// GEMM over one KC-k chunk: acc[p][g] += x2[k][pair p] * w[k][cu + 128g]
// xaddr: byte addr of pair0 at k0 (already + 32*bgrp); waddr: + cu*8.
__device__ __forceinline__ void gemm_chunk(uint32_t xaddr, uint32_t waddr,
                                           unsigned long long (&acc)[4][4])
{
#pragma unroll
    for (int kk = 0; kk < KC; ++kk) {
        unsigned long long xa, xb, xc, xd, w0, w1, w2, w3;
        asm volatile("ld.shared.v2.u64 {%0, %1}, [%2];" : "=l"(xa), "=l"(xb) : "r"(xaddr));
        asm volatile("ld.shared.v2.u64 {%0, %1}, [%2];" : "=l"(xc), "=l"(xd) : "r"(xaddr + 16));
        asm volatile("ld.shared.b64 %0, [%1];" : "=l"(w0) : "r"(waddr));
        asm volatile("ld.shared.b64 %0, [%1];" : "=l"(w1) : "r"(waddr + 1024));
        asm volatile("ld.shared.b64 %0, [%1];" : "=l"(w2) : "r"(waddr + 2048));
        asm volatile("ld.shared.b64 %0, [%1];" : "=l"(w3) : "r"(waddr + 3072));
        asm("fma.rn.f32x2 %0, %1, %2, %0;" : "+l"(acc[0][0]) : "l"(xa), "l"(w0));
        asm("fma.rn.f32x2 %0, %1, %2, %0;" : "+l"(acc[1][0]) : "l"(xb), "l"(w0));
        asm("fma.rn.f32x2 %0, %1, %2, %0;" : "+l"(acc[2][0]) : "l"(xc), "l"(w0));
        asm("fma.rn.f32x2 %0, %1, %2, %0;" : "+l"(acc[3][0]) : "l"(xd), "l"(w0));
        asm("fma.rn.f32x2 %0, %1, %2, %0;" : "+l"(acc[0][1]) : "l"(xa), "l"(w1));
        asm("fma.rn.f32x2 %0, %1, %2, %0;" : "+l"(acc[1][1]) : "l"(xb), "l"(w1));
        asm("fma.rn.f32x2 %0, %1, %2, %0;" : "+l"(acc[2][1]) : "l"(xc), "l"(w1));
        asm("fma.rn.f32x2 %0, %1, %2, %0;" : "+l"(acc[3][1]) : "l"(xd), "l"(w1));
        asm("fma.rn.f32x2 %0, %1, %2, %0;" : "+l"(acc[0][2]) : "l"(xa), "l"(w2));
        asm("fma.rn.f32x2 %0, %1, %2, %0;" : "+l"(acc[1][2]) : "l"(xb), "l"(w2));
        asm("fma.rn.f32x2 %0, %1, %2, %0;" : "+l"(acc[2][2]) : "l"(xc), "l"(w2));
        asm("fma.rn.f32x2 %0, %1, %2, %0;" : "+l"(acc[3][2]) : "l"(xd), "l"(w2));
        asm("fma.rn.f32x2 %0, %1, %2, %0;" : "+l"(acc[0][3]) : "l"(xa), "l"(w3));
        asm("fma.rn.f32x2 %0, %1, %2, %0;" : "+l"(acc[1][3]) : "l"(xb), "l"(w3));
        asm("fma.rn.f32x2 %0, %1, %2, %0;" : "+l"(acc[2][3]) : "l"(xc), "l"(w3));
        asm("fma.rn.f32x2 %0, %1, %2, %0;" : "+l"(acc[3][3]) : "l"(xd), "l"(w3));
        xaddr += ROWBYTES;
        waddr += GATES * 8;
    }
}

// Gates -> nonlinearity -> cell update -> h stores.
// acc[p][0..3] = (i,f,g,o) pre-activations for unit cu, batch pair 4*bgrp+p.
__device__ __forceinline__ void lstm_pointwise(unsigned long long (&acc)[4][4],
                                               float (&cs)[4][2],
                                               uint32_t dstA, uint32_t dstB, bool dual,
                                               int bgrp)
{
#pragma unroll
    for (int p = 0; p < 4; ++p) {
        float ilo, ihi, flo, fhi, glo, ghi, olo, ohi;
        unpack2(acc[p][0], ilo, ihi);
        unpack2(acc[p][1], flo, fhi);
        unpack2(acc[p][2], glo, ghi);
        unpack2(acc[p][3], olo, ohi);
        float clo = fsig(flo) * cs[p][0] + fsig(ilo) * ftanh_(glo);
        float chi = fsig(fhi) * cs[p][1] + fsig(ihi) * ftanh_(ghi);
        cs[p][0] = clo;
        cs[p][1] = chi;
        unsigned long long hp = pack2(fsig(olo) * ftanh_(clo), fsig(ohi) * ftanh_(chi));
        uint32_t off = 32u * bgrp + 8u * p;
        asm volatile("st.shared.b64 [%0], %1;" :: "r"(dstA + off), "l"(hp) : "memory");
        if (dual)
            asm volatile("st.shared.b64 [%0], %1;" :: "r"(dstB + off), "l"(hp) : "memory");
    }
}

// ---------------------------------------------------------------------------
__global__ void __launch_bounds__(NTHREAD, 1)
noteaxis_lstm(const float* __restrict__ nf, const float* __restrict__ tg,
              float* __restrict__ out)
{
    extern __shared__ float smem[];
    const int tid  = threadIdx.x;
    const int cu   = tid >> 2;   // 0..127 : unit owned by this thread
    const int bgrp = tid & 3;    // 0..3   : batch-pair group (pairs 4*bgrp..4*bgrp+3)
    const int b0   = blockIdx.x * BT;

    const uint32_t sbase = (uint32_t)__cvta_generic_to_shared(smem);
    const uint32_t sx0   = sbase;
    const uint32_t sx1   = sbase + OFF_X1 * 4;
    const uint32_t sw    = sbase + OFF_W  * 4;

    // Kick first weight chunk (layer0 chunk0 -> buffer 0) before anything else.
    prefetch_chunk(sw, g_Wt0, tid);

    // Zero both sX regions (h rows start at 0); stage biases / output weights.
    for (int i = tid; i < OFF_W; i += NTHREAD) smem[i] = 0.0f;
    {
        float2* bs0 = reinterpret_cast<float2*>(smem + OFF_B0D);
        float2* bs1 = reinterpret_cast<float2*>(smem + OFF_B1D);
        if (tid < GATES) { bs0[tid] = g_b0d[tid]; bs1[tid] = g_b1d[tid]; }
    }
    if (tid < UNITS) smem[OFF_WO + tid] = g_wout[tid];
    if (tid == 0)    smem[OFF_BO] = g_bout[0];

    float cs0[4][2], cs1[4][2];
#pragma unroll
    for (int p = 0; p < 4; ++p) {
        cs0[p][0] = 0.0f; cs0[p][1] = 0.0f;
        cs1[p][0] = 0.0f; cs1[p][1] = 0.0f;
    }

    __syncthreads();

    int parity = 0;          // smem buffer holding the next chunk to consume
    const uint32_t xoff = 32u * bgrp;
    const uint32_t woff = (uint32_t)cu * 8u;

    for (int t = 0; t < NSTEP; ++t) {
        // ---- stage x_t into sX0 rows 0..127, layout [k][b] ----------------
#pragma unroll
        for (int i = 0; i < 8; ++i) {
            int idx = tid + i * NTHREAD;     // 0..4095
            int b = idx >> 7;                // 0..31
            int f = idx & 127;               // 0..127
            float v;
            if (f < FDIM)
                v = nf[((b0 + b) * NSTEP + t) * FDIM + f];
            else
                v = (t > 0) ? tg[(b0 + b) * NSTEP + (t - 1)] : 0.0f;
            smem[OFF_X0 + f * ROWPAD + b] = v;
        }

        unsigned long long acc[4][4];

        // ================= layer 0 : gates = [x|h0] @ Wt0 + b0 =============
        {
            uint32_t baddr = sbase + OFF_B0D * 4 + woff;
#pragma unroll
            for (int g = 0; g < 4; ++g) {
                unsigned long long bp;
                asm volatile("ld.shared.b64 %0, [%1];" : "=l"(bp) : "r"(baddr + (uint32_t)g * 1024u));
                acc[0][g] = bp; acc[1][g] = bp; acc[2][g] = bp; acc[3][g] = bp;
            }
        }
        for (int ch = 0; ch < NCHUNK; ++ch) {
            asm volatile("cp.async.wait_group 0;" ::: "memory");
            __syncthreads();   // chunk ch visible; prev gemm done -> other buf free
            const float2* nxt = (ch < NCHUNK - 1) ? (g_Wt0 + (size_t)(ch + 1) * CHUNK_F2)
                                                  : g_Wt1;
            prefetch_chunk(sw + (uint32_t)(parity ^ 1) * CHUNK_BYTES, nxt, tid);
            gemm_chunk(sx0 + (uint32_t)(ch * KC) * ROWBYTES + xoff,
                       sw + (uint32_t)parity * CHUNK_BYTES + woff, acc);
            parity ^= 1;
        }
        __syncthreads();   // all warps done reading h0 rows before overwrite
        // h0 -> sX0 rows 128..255 (recurrent) and sX1 rows 0..127 (layer1 in)
        lstm_pointwise(acc, cs0,
                       sx0 + (uint32_t)(128 + cu) * ROWBYTES,
                       sx1 + (uint32_t)cu * ROWBYTES, true, bgrp);

        // ================= layer 1 : gates = [h0|h1] @ Wt1 + b1 ============
        {
            uint32_t baddr = sbase + OFF_B1D * 4 + woff;
#pragma unroll
            for (int g = 0; g < 4; ++g) {
                unsigned long long bp;
                asm volatile("ld.shared.b64 %0, [%1];" : "=l"(bp) : "r"(baddr + (uint32_t)g * 1024u));
                acc[0][g] = bp; acc[1][g] = bp; acc[2][g] = bp; acc[3][g] = bp;
            }
        }
        for (int ch = 0; ch < NCHUNK; ++ch) {
            asm volatile("cp.async.wait_group 0;" ::: "memory");
            __syncthreads();
            const float2* nxt = (ch < NCHUNK - 1) ? (g_Wt1 + (size_t)(ch + 1) * CHUNK_F2)
                                                  : g_Wt0;   // next step's layer0
            prefetch_chunk(sw + (uint32_t)(parity ^ 1) * CHUNK_BYTES, nxt, tid);
            gemm_chunk(sx1 + (uint32_t)(ch * KC) * ROWBYTES + xoff,
                       sw + (uint32_t)parity * CHUNK_BYTES + woff, acc);
            parity ^= 1;
        }
        __syncthreads();
        // h1 -> sX1 rows 128..255 (recurrent + output source)
        lstm_pointwise(acc, cs1,
                       sx1 + (uint32_t)(128 + cu) * ROWBYTES, 0u, false, bgrp);
        __syncthreads();   // h1 visible to output epilogue

        // ---------------- output: sigmoid(h1 . wout + bout) ---------------
        {
            int rowb = tid >> 4;   // 0..31
            int l16  = tid & 15;
            float s = 0.0f;
#pragma unroll
            for (int jj = 0; jj < 8; ++jj) {
                int u = l16 + 16 * jj;
                s += smem[OFF_X1 + (128 + u) * ROWPAD + rowb] * smem[OFF_WO + u];
            }
            s += __shfl_xor_sync(0xffffffffu, s, 1);
            s += __shfl_xor_sync(0xffffffffu, s, 2);
            s += __shfl_xor_sync(0xffffffffu, s, 4);
            s += __shfl_xor_sync(0xffffffffu, s, 8);
            if (l16 == 0)
                out[(b0 + rowb) * NSTEP + t] = fsig(s + smem[OFF_BO]);
        }
        // Next-step staging writes only sX0 rows 0..127 (disjoint from the
        // sX1 h-rows read above); layer0 iter0's sync orders everything else.
    }
}

// ---------------------------------------------------------------------------
extern "C" void kernel_launch(void* const* d_in, const int* in_sizes, int n_in,
                              void* d_out, int out_size)
{
    const float* nf   = (const float*)d_in[0];   // note_features [B,N,F]
    const float* tg   = (const float*)d_in[1];   // targets       [B,N]
    const float* wih0 = (const float*)d_in[2];
    const float* whh0 = (const float*)d_in[3];
    const float* bih0 = (const float*)d_in[4];
    const float* bhh0 = (const float*)d_in[5];
    const float* wih1 = (const float*)d_in[6];
    const float* whh1 = (const float*)d_in[7];
    const float* bih1 = (const float*)d_in[8];
    const float* bhh1 = (const float*)d_in[9];
    const float* wout = (const float*)d_in[10];
    const float* bout = (const float*)d_in[11];
    float* out = (float*)d_out;

    cudaFuncSetAttribute(noteaxis_lstm, cudaFuncAttributeMaxDynamicSharedMemorySize, SMEM_BYTES);

    noteaxis_prep<<<(KDIM * GATES + 255) / 256, 256>>>(wih0, whh0, bih0, bhh0,
                                                       wih1, whh1, bih1, bhh1,
                                                       wout, bout);
    noteaxis_lstm<<<NCTA, NTHREAD, SMEM_BYTES>>>(nf, tg, out);
}

// round 7
// speedup vs baseline: 1.0682x; 1.0682x over previous
#include <cuda_runtime.h>
#include <cstdint>

// ---------------------------------------------------------------------------
// NoteAxis: 2-layer LSTM, B=4096, U=128, 128 steps, teacher-forced.
// Persistent fp32 kernel, fma.rn.f32x2 packing TWO OUTPUT COLUMNS (a unit
// pair) per register. Weights load as natural float2 (no duplication, no
// movs); x is duplicated in SMEM ((x,x) pairs) at staging time.
// 128 CTAs x 256 threads; CTA owns 32 batch rows for all 128 steps.
// Thread tile: 2 units x 4 gates x 8 batch rows -> acc[8][4] f32x2; cell
// state for both layers lives in registers the whole kernel.
// Weights streamed L2->SMEM in 32KB chunks, triple-buffered cp.async, ONE
// __syncthreads per chunk.
// ---------------------------------------------------------------------------

#define B_TOTAL   4096
#define NSTEP     128
#define FDIM      127
#define UNITS     128
#define GATES     512
#define KDIM      256
#define BT        32
#define NCTA      (B_TOTAL / BT)       // 128
#define NTHREAD   256
#define KC        16                   // k rows per weight chunk
#define NCHUNK    (KDIM / KC)          // 16 per layer
#define SEQLEN    (2 * NCHUNK)         // 32 chunks per step (both layers)
#define CHUNK_FLOATS (KC * GATES)      // 8192
#define CHUNK_BYTES  (CHUNK_FLOATS * 4)// 32768

// x region: rows 0..127 = x_t, 128..255 = h0, 256..383 = h1.
// Each row: 32 batch values DUPLICATED ((v,v) f32 pairs) in 4 bank-swizzled
// slices of 8 rows: slice b>>3 at byte offset (b>>3)*64 + ((b>>3)>>1)*16.
#define XROWF     68                   // floats per row (272 B)
#define XROWB     272
#define NXROW     384

// shared layout (float offsets)
#define OFF_X     0
#define OFF_W     (NXROW * XROWF)              // 26112
#define OFF_B0    (OFF_W + 3 * CHUNK_FLOATS)   // 50688
#define OFF_B1    (OFF_B0 + GATES)             // 51200
#define OFF_WO    (OFF_B1 + GATES)             // 51712
#define OFF_BO    (OFF_WO + UNITS)             // 51840
#define SMEM_FLOATS (OFF_BO + 4)               // 51844
#define SMEM_BYTES  (SMEM_FLOATS * 4)          // 207376 (~202.5 KB)

// ---------------- persistent device scratch (no runtime alloc) -------------
__device__ float g_Wt0[KDIM * GATES];   // [k][c] transposed, NOT duplicated
__device__ float g_Wt1[KDIM * GATES];
__device__ float g_b0[GATES];           // b_ih + b_hh
__device__ float g_b1[GATES];
__device__ float g_wout[UNITS];
__device__ float g_bout[1];

// ---------------------------------------------------------------------------
__global__ void noteaxis_prep(const float* __restrict__ wih0, const float* __restrict__ whh0,
                              const float* __restrict__ bih0, const float* __restrict__ bhh0,
                              const float* __restrict__ wih1, const float* __restrict__ whh1,
                              const float* __restrict__ bih1, const float* __restrict__ bhh1,
                              const float* __restrict__ wout, const float* __restrict__ bout)
{
    int idx = blockIdx.x * blockDim.x + threadIdx.x;
    if (idx < KDIM * GATES) {
        int k = idx >> 9;
        int c = idx & 511;
        g_Wt0[idx] = (k < UNITS) ? wih0[c * UNITS + k] : whh0[c * UNITS + (k - UNITS)];
        g_Wt1[idx] = (k < UNITS) ? wih1[c * UNITS + k] : whh1[c * UNITS + (k - UNITS)];
    }
    if (idx < GATES) {
        g_b0[idx] = bih0[idx] + bhh0[idx];
        g_b1[idx] = bih1[idx] + bhh1[idx];
    }
    if (idx < UNITS) g_wout[idx] = wout[idx];
    if (idx == 0)    g_bout[0]   = bout[0];
}

// ---------------------------------------------------------------------------
__device__ __forceinline__ float ftanh_(float x) {
    float r;
    asm("tanh.approx.f32 %0, %1;" : "=f"(r) : "f"(x));
    return r;
}
__device__ __forceinline__ float fsig(float x) {
    return fmaf(0.5f, ftanh_(0.5f * x), 0.5f);
}
__device__ __forceinline__ void unpack2(unsigned long long v, float& lo, float& hi) {
    asm("mov.b64 {%0, %1}, %2;" : "=f"(lo), "=f"(hi) : "l"(v));
}
__device__ __forceinline__ unsigned long long pack2(float lo, float hi) {
    unsigned long long v;
    asm("mov.b64 %0, {%1, %2};" : "=l"(v) : "f"(lo), "f"(hi));
    return v;
}

// byte offset of (dup'd) batch element b within an x row
__device__ __forceinline__ uint32_t bslice(int b) {
    int s = b >> 3;
    return (uint32_t)(s * 64 + (s >> 1) * 16 + (b & 7) * 8);
}

// Stage one KC x 512 weight chunk (32 KB) gmem -> smem via cp.async.cg.
__device__ __forceinline__ void prefetch_chunk(uint32_t dst_smem, const float* __restrict__ src, int tid) {
    const char* s = reinterpret_cast<const char*>(src) + tid * 16;
    uint32_t d = dst_smem + tid * 16;
#pragma unroll
    for (int r = 0; r < 8; ++r) {
        asm volatile("cp.async.cg.shared.global [%0], [%1], 16;" :: "r"(d), "l"(s) : "memory");
        d += NTHREAD * 16;
        s += NTHREAD * 16;
    }
    asm volatile("cp.async.commit_group;" ::: "memory");
}

__device__ __forceinline__ const float* chunk_src(int s) {   // s in 0..31
    return (s < NCHUNK) ? (g_Wt0 + (size_t)s * CHUNK_FLOATS)
                        : (g_Wt1 + (size_t)(s - NCHUNK) * CHUNK_FLOATS);
}

// GEMM over one KC-k chunk.
// xaddr: byte addr of this thread's slice (rows 8*bgrp..+7, dup'd) at k0.
// waddr: byte addr of col pair (2*wgrp, 2*wgrp+1) gate 0 at k0.
// acc[r][g] (f32x2 over the unit pair) += x[r] * w[g]
__device__ __forceinline__ void gemm_chunk(uint32_t xaddr, uint32_t waddr,
                                           unsigned long long (&acc)[8][4])
{
#pragma unroll
    for (int kk = 0; kk < KC; ++kk) {
        unsigned long long x0, x1, x2, x3, x4, x5, x6, x7;
        unsigned long long w0, w1, w2, w3;
        asm volatile("ld.shared.v2.u64 {%0, %1}, [%2];" : "=l"(x0), "=l"(x1) : "r"(xaddr));
        asm volatile("ld.shared.v2.u64 {%0, %1}, [%2];" : "=l"(x2), "=l"(x3) : "r"(xaddr + 16));
        asm volatile("ld.shared.v2.u64 {%0, %1}, [%2];" : "=l"(x4), "=l"(x5) : "r"(xaddr + 32));
        asm volatile("ld.shared.v2.u64 {%0, %1}, [%2];" : "=l"(x6), "=l"(x7) : "r"(xaddr + 48));
        asm volatile("ld.shared.b64 %0, [%1];" : "=l"(w0) : "r"(waddr));
        asm volatile("ld.shared.b64 %0, [%1];" : "=l"(w1) : "r"(waddr + 512));
        asm volatile("ld.shared.b64 %0, [%1];" : "=l"(w2) : "r"(waddr + 1024));
        asm volatile("ld.shared.b64 %0, [%1];" : "=l"(w3) : "r"(waddr + 1536));
        asm("fma.rn.f32x2 %0, %1, %2, %0;" : "+l"(acc[0][0]) : "l"(x0), "l"(w0));
        asm("fma.rn.f32x2 %0, %1, %2, %0;" : "+l"(acc[1][0]) : "l"(x1), "l"(w0));
        asm("fma.rn.f32x2 %0, %1, %2, %0;" : "+l"(acc[2][0]) : "l"(x2), "l"(w0));
        asm("fma.rn.f32x2 %0, %1, %2, %0;" : "+l"(acc[3][0]) : "l"(x3), "l"(w0));
        asm("fma.rn.f32x2 %0, %1, %2, %0;" : "+l"(acc[4][0]) : "l"(x4), "l"(w0));
        asm("fma.rn.f32x2 %0, %1, %2, %0;" : "+l"(acc[5][0]) : "l"(x5), "l"(w0));
        asm("fma.rn.f32x2 %0, %1, %2, %0;" : "+l"(acc[6][0]) : "l"(x6), "l"(w0));
        asm("fma.rn.f32x2 %0, %1, %2, %0;" : "+l"(acc[7][0]) : "l"(x7), "l"(w0));
        asm("fma.rn.f32x2 %0, %1, %2, %0;" : "+l"(acc[0][1]) : "l"(x0), "l"(w1));
        asm("fma.rn.f32x2 %0, %1, %2, %0;" : "+l"(acc[1][1]) : "l"(x1), "l"(w1));
        asm("fma.rn.f32x2 %0, %1, %2, %0;" : "+l"(acc[2][1]) : "l"(x2), "l"(w1));
        asm("fma.rn.f32x2 %0, %1, %2, %0;" : "+l"(acc[3][1]) : "l"(x3), "l"(w1));
        asm("fma.rn.f32x2 %0, %1, %2, %0;" : "+l"(acc[4][1]) : "l"(x4), "l"(w1));
        asm("fma.rn.f32x2 %0, %1, %2, %0;" : "+l"(acc[5][1]) : "l"(x5), "l"(w1));
        asm("fma.rn.f32x2 %0, %1, %2, %0;" : "+l"(acc[6][1]) : "l"(x6), "l"(w1));
        asm("fma.rn.f32x2 %0, %1, %2, %0;" : "+l"(acc[7][1]) : "l"(x7), "l"(w1));
        asm("fma.rn.f32x2 %0, %1, %2, %0;" : "+l"(acc[0][2]) : "l"(x0), "l"(w2));
        asm("fma.rn.f32x2 %0, %1, %2, %0;" : "+l"(acc[1][2]) : "l"(x1), "l"(w2));
        asm("fma.rn.f32x2 %0, %1, %2, %0;" : "+l"(acc[2][2]) : "l"(x2), "l"(w2));
        asm("fma.rn.f32x2 %0, %1, %2, %0;" : "+l"(acc[3][2]) : "l"(x3), "l"(w2));
        asm("fma.rn.f32x2 %0, %1, %2, %0;" : "+l"(acc[4][2]) : "l"(x4), "l"(w2));
        asm("fma.rn.f32x2 %0, %1, %2, %0;" : "+l"(acc[5][2]) : "l"(x5), "l"(w2));
        asm("fma.rn.f32x2 %0, %1, %2, %0;" : "+l"(acc[6][2]) : "l"(x6), "l"(w2));
        asm("fma.rn.f32x2 %0, %1, %2, %0;" : "+l"(acc[7][2]) : "l"(x7), "l"(w2));
        asm("fma.rn.f32x2 %0, %1, %2, %0;" : "+l"(acc[0][3]) : "l"(x0), "l"(w3));
        asm("fma.rn.f32x2 %0, %1, %2, %0;" : "+l"(acc[1][3]) : "l"(x1), "l"(w3));
        asm("fma.rn.f32x2 %0, %1, %2, %0;" : "+l"(acc[2][3]) : "l"(x2), "l"(w3));
        asm("fma.rn.f32x2 %0, %1, %2, %0;" : "+l"(acc[3][3]) : "l"(x3), "l"(w3));
        asm("fma.rn.f32x2 %0, %1, %2, %0;" : "+l"(acc[4][3]) : "l"(x4), "l"(w3));
        asm("fma.rn.f32x2 %0, %1, %2, %0;" : "+l"(acc[5][3]) : "l"(x5), "l"(w3));
        asm("fma.rn.f32x2 %0, %1, %2, %0;" : "+l"(acc[6][3]) : "l"(x6), "l"(w3));
        asm("fma.rn.f32x2 %0, %1, %2, %0;" : "+l"(acc[7][3]) : "l"(x7), "l"(w3));
        xaddr += XROWB;
        waddr += GATES * 4;
    }
}

// Gates -> nonlinearity -> cell update -> dup'd h stores.
// acc[r][g] = pre-activation f32x2 (unit u0, u0+1) of gate g, batch row
// r_abs = 8*bgrp + r. hrow0: byte addr of (h row u0) + this thread's slice.
__device__ __forceinline__ void lstm_pointwise(unsigned long long (&acc)[8][4],
                                               float (&cs)[8][2],
                                               uint32_t hrow0)
{
#pragma unroll
    for (int r = 0; r < 8; ++r) {
        float i0, i1, f0, f1, g0, g1, o0, o1;
        unpack2(acc[r][0], i0, i1);
        unpack2(acc[r][1], f0, f1);
        unpack2(acc[r][2], g0, g1);
        unpack2(acc[r][3], o0, o1);
        float c0 = fsig(f0) * cs[r][0] + fsig(i0) * ftanh_(g0);
        float c1 = fsig(f1) * cs[r][1] + fsig(i1) * ftanh_(g1);
        cs[r][0] = c0;
        cs[r][1] = c1;
        float h0 = fsig(o0) * ftanh_(c0);
        float h1 = fsig(o1) * ftanh_(c1);
        asm volatile("st.shared.b64 [%0], %1;" :: "r"(hrow0 + (uint32_t)(r * 8)),
                     "l"(pack2(h0, h0)) : "memory");
        asm volatile("st.shared.b64 [%0], %1;" :: "r"(hrow0 + (uint32_t)(XROWB + r * 8)),
                     "l"(pack2(h1, h1)) : "memory");
    }
}

// ---------------------------------------------------------------------------
__global__ void __launch_bounds__(NTHREAD, 1)
noteaxis_lstm(const float* __restrict__ nf, const float* __restrict__ tg,
              float* __restrict__ out)
{
    extern __shared__ float smem[];
    const int tid  = threadIdx.x;
    const int wgrp = tid >> 2;   // 0..63 : unit pair {2*wgrp, 2*wgrp+1}
    const int bgrp = tid & 3;    // 0..3  : batch rows 8*bgrp..8*bgrp+7
    const int b0   = blockIdx.x * BT;

    const uint32_t sbase = (uint32_t)__cvta_generic_to_shared(smem);
    const uint32_t sx    = sbase;                 // 384-row x/h region
    const uint32_t sw    = sbase + OFF_W * 4;     // 3 weight buffers

    // Kick the first two weight chunks (layer0 chunks 0,1 -> bufs 0,1).
    prefetch_chunk(sw, chunk_src(0), tid);
    prefetch_chunk(sw + CHUNK_BYTES, chunk_src(1), tid);

    // Zero the x/h region; stage biases / output weights.
    for (int i = tid; i < OFF_W; i += NTHREAD) smem[i] = 0.0f;
    for (int i = tid; i < GATES; i += NTHREAD) {
        smem[OFF_B0 + i] = g_b0[i];
        smem[OFF_B1 + i] = g_b1[i];
    }
    if (tid < UNITS) smem[OFF_WO + tid] = g_wout[tid];
    if (tid == 0)    smem[OFF_BO] = g_bout[0];

    float cs0[8][2], cs1[8][2];
#pragma unroll
    for (int r = 0; r < 8; ++r) {
        cs0[r][0] = 0.0f; cs0[r][1] = 0.0f;
        cs1[r][0] = 0.0f; cs1[r][1] = 0.0f;
    }

    __syncthreads();

    const uint32_t xoff = bslice(8 * bgrp);            // this thread's slice
    const uint32_t woff = (uint32_t)wgrp * 8u;         // col pair byte offset
    const uint32_t h0row = sx + (uint32_t)(128 + 2 * wgrp) * XROWB + xoff;
    const uint32_t h1row = sx + (uint32_t)(256 + 2 * wgrp) * XROWB + xoff;

    int pseq = 2;    // next chunk (in 0..31 step sequence) to prefetch
    int gbuf = 0;    // buffer index of the next chunk to consume

    for (int t = 0; t < NSTEP; ++t) {
        // ---- stage x_t (dup'd) into rows 0..127 ---------------------------
#pragma unroll
        for (int i = 0; i < 16; ++i) {
            int idx = tid + i * NTHREAD;     // 0..4095
            int b = idx >> 7;                // 0..31
            int f = idx & 127;               // 0..127
            float v;
            if (f < FDIM)
                v = nf[((b0 + b) * NSTEP + t) * FDIM + f];
            else
                v = (t > 0) ? tg[(b0 + b) * NSTEP + (t - 1)] : 0.0f;
            asm volatile("st.shared.b64 [%0], %1;"
                         :: "r"(sx + (uint32_t)f * XROWB + bslice(b)),
                            "l"(pack2(v, v)) : "memory");
        }

        unsigned long long acc[8][4];

        // ================= layer 0 : gates = [x|h0] @ Wt0 + b0 =============
        {
            const float2* bp = reinterpret_cast<const float2*>(smem + OFF_B0);
#pragma unroll
            for (int g = 0; g < 4; ++g) {
                float2 bv = bp[64 * g + wgrp];
                unsigned long long b2 = pack2(bv.x, bv.y);
#pragma unroll
                for (int r = 0; r < 8; ++r) acc[r][g] = b2;
            }
        }
        for (int ch = 0; ch < NCHUNK; ++ch) {
            asm volatile("cp.async.wait_group 1;" ::: "memory");
            __syncthreads();   // chunk ch visible; target buf fully consumed
            int tbuf = gbuf + 2; if (tbuf >= 3) tbuf -= 3;
            prefetch_chunk(sw + (uint32_t)tbuf * CHUNK_BYTES, chunk_src(pseq), tid);
            if (++pseq == SEQLEN) pseq = 0;
            gemm_chunk(sx + (uint32_t)(ch * KC) * XROWB + xoff,
                       sw + (uint32_t)gbuf * CHUNK_BYTES + woff, acc);
            if (++gbuf == 3) gbuf = 0;
        }
        __syncthreads();   // all warps finished reading h0(prev) rows
        lstm_pointwise(acc, cs0, h0row);   // h0 -> rows 128..255 (dup'd)

        // ================= layer 1 : gates = [h0|h1] @ Wt1 + b1 ============
        {
            const float2* bp = reinterpret_cast<const float2*>(smem + OFF_B1);
#pragma unroll
            for (int g = 0; g < 4; ++g) {
                float2 bv = bp[64 * g + wgrp];
                unsigned long long b2 = pack2(bv.x, bv.y);
#pragma unroll
                for (int r = 0; r < 8; ++r) acc[r][g] = b2;
            }
        }
        for (int ch = 0; ch < NCHUNK; ++ch) {
            asm volatile("cp.async.wait_group 1;" ::: "memory");
            __syncthreads();   // also makes h0 stores visible at ch==0
            int tbuf = gbuf + 2; if (tbuf >= 3) tbuf -= 3;
            prefetch_chunk(sw + (uint32_t)tbuf * CHUNK_BYTES, chunk_src(pseq), tid);
            if (++pseq == SEQLEN) pseq = 0;
            gemm_chunk(sx + (uint32_t)(128 + ch * KC) * XROWB + xoff,
                       sw + (uint32_t)gbuf * CHUNK_BYTES + woff, acc);
            if (++gbuf == 3) gbuf = 0;
        }
        __syncthreads();   // all warps finished reading h1(prev) rows
        lstm_pointwise(acc, cs1, h1row);   // h1 -> rows 256..383 (dup'd)
        __syncthreads();   // h1 visible to epilogue

        // ---------------- output: sigmoid(h1 . wout + bout) ---------------
        {
            int rowb = tid >> 3;   // batch 0..31
            int l8   = tid & 7;
            uint32_t so = bslice(rowb) >> 2;   // float index of dup'd value
            float s = 0.0f;
#pragma unroll
            for (int jj = 0; jj < 16; ++jj) {
                int u = l8 + 8 * jj;
                s += smem[(256 + u) * XROWF + so] * smem[OFF_WO + u];
            }
            s += __shfl_xor_sync(0xffffffffu, s, 1);
            s += __shfl_xor_sync(0xffffffffu, s, 2);
            s += __shfl_xor_sync(0xffffffffu, s, 4);
            if (l8 == 0)
                out[(b0 + rowb) * NSTEP + t] = fsig(s + smem[OFF_BO]);
        }
        // Next-step staging writes rows 0..127 only (epilogue reads rows
        // 256..383); layer0 chunk0's sync orders everything else.
    }
}

// ---------------------------------------------------------------------------
extern "C" void kernel_launch(void* const* d_in, const int* in_sizes, int n_in,
                              void* d_out, int out_size)
{
    const float* nf   = (const float*)d_in[0];   // note_features [B,N,F]
    const float* tg   = (const float*)d_in[1];   // targets       [B,N]
    const float* wih0 = (const float*)d_in[2];
    const float* whh0 = (const float*)d_in[3];
    const float* bih0 = (const float*)d_in[4];
    const float* bhh0 = (const float*)d_in[5];
    const float* wih1 = (const float*)d_in[6];
    const float* whh1 = (const float*)d_in[7];
    const float* bih1 = (const float*)d_in[8];
    const float* bhh1 = (const float*)d_in[9];
    const float* wout = (const float*)d_in[10];
    const float* bout = (const float*)d_in[11];
    float* out = (float*)d_out;

    cudaFuncSetAttribute(noteaxis_lstm, cudaFuncAttributeMaxDynamicSharedMemorySize, SMEM_BYTES);

    noteaxis_prep<<<(KDIM * GATES + 255) / 256, 256>>>(wih0, whh0, bih0, bhh0,
                                                       wih1, whh1, bih1, bhh1,
                                                       wout, bout);
    noteaxis_lstm<<<NCTA, NTHREAD, SMEM_BYTES>>>(nf, tg, out);
}